// round 15
// baseline (speedup 1.0000x reference)
#include <cuda_runtime.h>
#include <cuda_fp16.h>
#include <cstdint>

// Problem constants (B=1)
#define L 768
#define C_IN 384
#define D 32          // C_OUTER
#define E 128         // C_OUT
#define EPS 1e-5f

// ---------------- scratch (no allocations allowed) ----------------
__device__ float g_right[L * D];
__device__ __align__(16) __half g_lh[L * D];   // left (fp16)

// ================= PTX helpers =================
__device__ __forceinline__ uint32_t smem_u32(const void* p) {
    uint32_t a;
    asm("{ .reg .u64 t; cvta.to.shared.u64 t, %1; cvt.u32.u64 %0, t; }" : "=r"(a) : "l"(p));
    return a;
}
__device__ __forceinline__ void ldsm_x4(uint32_t* r, uint32_t addr) {
    asm volatile("ldmatrix.sync.aligned.m8n8.x4.shared.b16 {%0,%1,%2,%3}, [%4];"
                 : "=r"(r[0]), "=r"(r[1]), "=r"(r[2]), "=r"(r[3]) : "r"(addr));
}
__device__ __forceinline__ void mma16816(float* c, const uint32_t* a, const uint32_t* b) {
    asm volatile("mma.sync.aligned.m16n8k16.row.col.f32.f16.f16.f32 "
                 "{%0,%1,%2,%3}, {%4,%5,%6,%7}, {%8,%9}, {%0,%1,%2,%3};"
                 : "+f"(c[0]), "+f"(c[1]), "+f"(c[2]), "+f"(c[3])
                 : "r"(a[0]), "r"(a[1]), "r"(a[2]), "r"(a[3]), "r"(b[0]), "r"(b[1]));
}
#define CP_ASYNC16(dst, src) \
    asm volatile("cp.async.ca.shared.global [%0], [%1], 16;" :: "r"(dst), "l"(src) : "memory")
#define CP_COMMIT()  asm volatile("cp.async.commit_group;" ::: "memory")
#define CP_WAIT0()   asm volatile("cp.async.wait_group 0;" ::: "memory")

// ---------------- Kernel A v3: LN + projections, 4 rows/block ----------------
// grid = 192, block = 256 (8 warps).
// Warp w handles (row r = w>>1, c-half h = w&1); lane = col-pair p.
// Each LDG.64 of w feeds 2 FMAs; ns reads are warp-uniform smem broadcasts.
__global__ void __launch_bounds__(256) ln_proj_kernel(
    const float* __restrict__ act, const float* __restrict__ mask,
    const float* __restrict__ nw, const float* __restrict__ nb,
    const float* __restrict__ wl, const float* __restrict__ bl,
    const float* __restrict__ wr, const float* __restrict__ br)
{
    __shared__ float ns[4 * C_IN];          // 6 KB normed rows
    __shared__ float2 red[256];             // half-sum reduction

    const int tid = threadIdx.x;
    const int lane = tid & 31;
    const int wid = tid >> 5;
    const int lbase = blockIdx.x * 4;

    // ---- LayerNorm: warps 0..3 own one row each (shuffle-only) ----
    if (wid < 4) {
        const int l = lbase + wid;
        const float* arow = act + (size_t)l * C_IN;
        float x[12];
        #pragma unroll
        for (int t = 0; t < 12; ++t) x[t] = arow[lane + t * 32];

        float s = 0.f;
        #pragma unroll
        for (int t = 0; t < 12; ++t) s += x[t];
        #pragma unroll
        for (int o = 16; o > 0; o >>= 1) s += __shfl_xor_sync(0xffffffffu, s, o);
        const float mu = s * (1.0f / C_IN);

        float v = 0.f;
        #pragma unroll
        for (int t = 0; t < 12; ++t) { const float d = x[t] - mu; v += d * d; }
        #pragma unroll
        for (int o = 16; o > 0; o >>= 1) v += __shfl_xor_sync(0xffffffffu, v, o);
        const float rstd = rsqrtf(v * (1.0f / C_IN) + EPS);

        float* nsr = ns + wid * C_IN;
        #pragma unroll
        for (int t = 0; t < 12; ++t) {
            const int c = lane + t * 32;
            nsr[c] = (x[t] - mu) * rstd * nw[c] + nb[c];
        }
    }
    __syncthreads();

    // ---- projections: thread = (row r, c-half h, col-pair p) ----
    const int r = tid >> 6;            // 0..3
    const int h = (tid >> 5) & 1;      // c-half (warp-uniform)
    const int p = lane;                // 0..15 left pairs, 16..31 right pairs
    const bool isL = p < 16;
    const int col = (p & 15) * 2;
    const float* wbase = (isL ? wl : wr) + (size_t)h * 192 * D + col;
    const float* nsr = ns + r * C_IN + h * 192;

    float a0 = 0.f, a1 = 0.f;
    #pragma unroll 8
    for (int c = 0; c < 192; ++c) {
        const float2 wv = *reinterpret_cast<const float2*>(wbase + c * D);
        const float nv = nsr[c];
        a0 = fmaf(nv, wv.x, a0);
        a1 = fmaf(nv, wv.y, a1);
    }
    red[tid] = make_float2(a0, a1);
    __syncthreads();

    if (h == 0) {
        const float2 o2 = red[tid + 32];
        a0 += o2.x; a1 += o2.y;
        const int l = lbase + r;
        const float m = mask[l];
        if (isL) {
            const float v0 = m * (a0 + bl[col]);
            const float v1 = m * (a1 + bl[col + 1]);
            g_lh[l * D + col]     = __float2half_rn(v0);
            g_lh[l * D + col + 1] = __float2half_rn(v1);
        } else {
            g_right[l * D + col]     = m * (a0 + br[col]);
            g_right[l * D + col + 1] = m * (a1 + br[col + 1]);
        }
    }
}

// ---------------- Kernel C: mma.sync batched GEMM (fp16, K=32) ----------------
// grid = (2 j-halves, L i), block = 256 (8 warps: 2 mw x 4 nq), 12 j-tiles of 32 rows
// A double-buffered via cp.async; B fragments hoisted; lin folded into MMA C-init;
// output staged through a DOUBLE-BUFFERED swizzled smem stage -> ONE bar per tile.
#define RSTRIDE 80
#define BTILEB  10240
#define ATILEB  2560           // 32 rows x 80 B
#define STAGEB  16384          // 32 rows x 512 B
#define SOFF_LIN   0
#define SOFF_B     512
#define SOFF_A0    (512 + BTILEB)
#define SOFF_A1    (512 + BTILEB + ATILEB)
#define SOFF_STG   (512 + BTILEB + 2 * ATILEB)       // 15872
#define SMEM_PAIR  (SOFF_STG + 2 * STAGEB)           // 48640

__global__ void __launch_bounds__(256, 4) pair_kernel(
    const float* __restrict__ wo, const float* __restrict__ bo,
    float* __restrict__ out)
{
    extern __shared__ char smem[];
    __shared__ float r_s[D];
    const uint32_t sb = smem_u32(smem);
    const uint32_t sB = sb + SOFF_B;
    float* lin_s = reinterpret_cast<float*>(smem + SOFF_LIN);

    const int tid = threadIdx.x;
    const int wid = tid >> 5;
    const int lane = tid & 31;
    const int mw = wid & 1;          // m position: rows mw*16 within 32-row tile
    const int nq = wid >> 1;         // e quadrant: cols nq*32
    const int i = blockIdx.y;
    const int jh = blockIdx.x;       // 0/1 j-half

    if (tid < D) r_s[tid] = g_right[i * D + tid];
    __syncthreads();

    // ---- build B tile in smem (threads 0..127) + lin ----
    if (tid < E) {
        const int e = tid;
        float acc = 0.0f;
        alignas(16) __half hi[D];
        #pragma unroll
        for (int d = 0; d < D; ++d) {
            const float w1 = wo[d * E + e];
            const float w2 = wo[(D + d) * E + e];
            const float rd = r_s[d];
            hi[d] = __float2half_rn(fmaf(rd, w1, w2));
            acc = fmaf(rd, w2, acc);
        }
        lin_s[e] = bo[e] - acc;
        const uint4* h4 = reinterpret_cast<const uint4*>(hi);
        char* rowp = smem + SOFF_B + e * RSTRIDE;
        #pragma unroll
        for (int c = 0; c < 4; ++c)
            *reinterpret_cast<uint4*>(rowp + c * 16) = h4[c];
    }

    // ---- first A tile (32 rows) via cp.async into buffer 0 ----
    const __half* gA = g_lh;
    const int jbase = jh * 384;
    if (tid < 128) {
        const int row = tid >> 2, c = tid & 3;
        CP_ASYNC16(sb + SOFF_A0 + row * RSTRIDE + c * 16,
                   (const char*)(gA + (jbase + row) * D) + c * 16);
    }
    CP_COMMIT();
    CP_WAIT0();
    __syncthreads();

    // ---- hoist B fragments (32 cols per warp, both k-tiles) ----
    uint32_t bfr[2][4][2];
    #pragma unroll
    for (int kt = 0; kt < 2; ++kt) {
        #pragma unroll
        for (int p = 0; p < 2; ++p) {
            const uint32_t er = nq * 32 + p * 16;
            const uint32_t row = er + (lane & 7) + ((lane >> 4) << 3);
            const uint32_t addr = sB + row * RSTRIDE + kt * 32 + (((lane >> 3) & 1) << 4);
            uint32_t r[4];
            ldsm_x4(r, addr);
            bfr[kt][2 * p][0] = r[0]; bfr[kt][2 * p][1] = r[1];
            bfr[kt][2 * p + 1][0] = r[2]; bfr[kt][2 * p + 1][1] = r[3];
        }
    }

    // per-lane lin pair for each n (folded into MMA C-init)
    float2 linv[4];
    #pragma unroll
    for (int n = 0; n < 4; ++n)
        linv[n] = reinterpret_cast<const float2*>(lin_s)[nq * 16 + n * 4 + (lane & 3)];

    for (int jt = 0; jt < 12; ++jt) {
        const int j0 = jbase + jt * 32;
        const uint32_t sA     = sb + ((jt & 1) ? SOFF_A1 : SOFF_A0);
        const uint32_t sAnext = sb + ((jt & 1) ? SOFF_A0 : SOFF_A1);
        const uint32_t sStage = sb + SOFF_STG + ((jt & 1) ? STAGEB : 0);

        // ---- mainloop: acc starts at lin; mma accumulates onto it ----
        float acc[4][4];
        #pragma unroll
        for (int n = 0; n < 4; ++n) {
            acc[n][0] = linv[n].x; acc[n][1] = linv[n].y;
            acc[n][2] = linv[n].x; acc[n][3] = linv[n].y;
        }

        #pragma unroll
        for (int kt = 0; kt < 2; ++kt) {
            const uint32_t jr = mw * 16 + (lane & 15);
            const uint32_t addr = sA + jr * RSTRIDE + kt * 32 + ((lane >> 4) << 4);
            uint32_t a[4];
            ldsm_x4(a, addr);
            #pragma unroll
            for (int n = 0; n < 4; ++n)
                mma16816(acc[n], a, bfr[kt][n]);
        }

        // ---- prefetch next A tile immediately (latency hidden under STS) ----
        const bool has_next = (jt < 11);
        if (has_next) {
            if (tid < 128) {
                const int j1 = j0 + 32;
                const int row = tid >> 2, c = tid & 3;
                CP_ASYNC16(sAnext + row * RSTRIDE + c * 16,
                           (const char*)(gA + (j1 + row) * D) + c * 16);
            }
            CP_COMMIT();
        }

        // ---- STS acc into this tile's stage buffer (conflict-free) ----
        #pragma unroll
        for (int h = 0; h < 2; ++h) {
            const uint32_t r = mw * 16 + (lane >> 2) + 8 * h;
            const uint32_t rbase = sStage + r * 512 + ((lane & 1) << 3);
            const uint32_t sw2 = (r & 7) << 1;
            #pragma unroll
            for (int n = 0; n < 4; ++n) {
                const uint32_t chunk = nq * 8 + n * 2 + ((lane & 3) >> 1);
                const uint32_t addr = rbase + ((chunk ^ sw2) << 4);
                asm volatile("st.shared.v2.f32 [%0], {%1,%2};"
                             :: "r"(addr), "f"(acc[n][2 * h]), "f"(acc[n][2 * h + 1]) : "memory");
            }
        }

        if (has_next) CP_WAIT0();
        __syncthreads();   // single barrier: stage visible + next A ready

        // ---- drain: pure LDS.128 -> STG.128, full 512B rows ----
        #pragma unroll
        for (int rr = 0; rr < 4; ++rr) {
            const uint32_t r2 = wid * 4 + rr;
            const uint32_t la = sStage + r2 * 512 + (((uint32_t)lane ^ ((r2 & 7) << 1)) << 4);
            float v0, v1, v2, v3;
            asm volatile("ld.shared.v4.f32 {%0,%1,%2,%3}, [%4];"
                         : "=f"(v0), "=f"(v1), "=f"(v2), "=f"(v3) : "r"(la));
            float4 v;
            v.x = v0; v.y = v1; v.z = v2; v.w = v3;
            *reinterpret_cast<float4*>(out + ((size_t)i * L + j0 + r2) * E + lane * 4) = v;
        }
    }
}

// ---------------- launch ----------------
extern "C" void kernel_launch(void* const* d_in, const int* in_sizes, int n_in,
                              void* d_out, int out_size)
{
    const float* act  = (const float*)d_in[0];
    const float* mask = (const float*)d_in[1];
    const float* nw   = (const float*)d_in[2];
    const float* nb   = (const float*)d_in[3];
    const float* wl   = (const float*)d_in[4];
    const float* bl   = (const float*)d_in[5];
    const float* wr   = (const float*)d_in[6];
    const float* br   = (const float*)d_in[7];
    const float* wo   = (const float*)d_in[8];
    const float* bo   = (const float*)d_in[9];
    float* out = (float*)d_out;

    cudaFuncSetAttribute(pair_kernel, cudaFuncAttributeMaxDynamicSharedMemorySize, SMEM_PAIR);

    ln_proj_kernel<<<L / 4, 256>>>(act, mask, nw, nb, wl, bl, wr, br);
    pair_kernel<<<dim3(2, L), 256, SMEM_PAIR>>>(wo, bo, out);
}

// round 16
// speedup vs baseline: 1.3298x; 1.3298x over previous
#include <cuda_runtime.h>
#include <cuda_fp16.h>
#include <cstdint>

// Problem constants (B=1)
#define L 768
#define C_IN 384
#define D 32          // C_OUTER
#define E 128         // C_OUT
#define EPS 1e-5f

// ---------------- scratch (no allocations allowed) ----------------
__device__ float g_right[L * D];
__device__ __align__(16) __half g_lh[L * D];   // left (fp16)

// ================= PTX helpers =================
__device__ __forceinline__ uint32_t smem_u32(const void* p) {
    uint32_t a;
    asm("{ .reg .u64 t; cvta.to.shared.u64 t, %1; cvt.u32.u64 %0, t; }" : "=r"(a) : "l"(p));
    return a;
}
__device__ __forceinline__ void ldsm_x4(uint32_t* r, uint32_t addr) {
    asm volatile("ldmatrix.sync.aligned.m8n8.x4.shared.b16 {%0,%1,%2,%3}, [%4];"
                 : "=r"(r[0]), "=r"(r[1]), "=r"(r[2]), "=r"(r[3]) : "r"(addr));
}
__device__ __forceinline__ void mma16816(float* c, const uint32_t* a, const uint32_t* b) {
    asm volatile("mma.sync.aligned.m16n8k16.row.col.f32.f16.f16.f32 "
                 "{%0,%1,%2,%3}, {%4,%5,%6,%7}, {%8,%9}, {%0,%1,%2,%3};"
                 : "+f"(c[0]), "+f"(c[1]), "+f"(c[2]), "+f"(c[3])
                 : "r"(a[0]), "r"(a[1]), "r"(a[2]), "r"(a[3]), "r"(b[0]), "r"(b[1]));
}
#define CP_ASYNC16(dst, src) \
    asm volatile("cp.async.ca.shared.global [%0], [%1], 16;" :: "r"(dst), "l"(src) : "memory")
#define CP_COMMIT()  asm volatile("cp.async.commit_group;" ::: "memory")
#define CP_WAIT0()   asm volatile("cp.async.wait_group 0;" ::: "memory")

// ---------------- Kernel A v4: LN + projections, 2 rows/block ----------------
// grid = 384, block = 256. R13 structure; each weight LDG feeds 2 FMAs (2 rows).
__global__ void __launch_bounds__(256) ln_proj_kernel(
    const float* __restrict__ act, const float* __restrict__ mask,
    const float* __restrict__ nw, const float* __restrict__ nb,
    const float* __restrict__ wl, const float* __restrict__ bl,
    const float* __restrict__ wr, const float* __restrict__ br)
{
    __shared__ float s_norm[2 * C_IN];
    __shared__ float2 red[256];

    const int tid = threadIdx.x;
    const int lane = tid & 31;
    const int wid = tid >> 5;
    const int l0 = blockIdx.x * 2;

    // ---- LayerNorm: warps 0..1 own one row each (shuffle-only) ----
    if (wid < 2) {
        const int l = l0 + wid;
        const float* arow = act + (size_t)l * C_IN;
        float x[12];
        #pragma unroll
        for (int t = 0; t < 12; ++t) x[t] = arow[lane + t * 32];

        float s = 0.f;
        #pragma unroll
        for (int t = 0; t < 12; ++t) s += x[t];
        #pragma unroll
        for (int o = 16; o > 0; o >>= 1) s += __shfl_xor_sync(0xffffffffu, s, o);
        const float mu = s * (1.0f / C_IN);

        float v = 0.f;
        #pragma unroll
        for (int t = 0; t < 12; ++t) { const float d = x[t] - mu; v += d * d; }
        #pragma unroll
        for (int o = 16; o > 0; o >>= 1) v += __shfl_xor_sync(0xffffffffu, v, o);
        const float rstd = rsqrtf(v * (1.0f / C_IN) + EPS);

        float* nsr = s_norm + wid * C_IN;
        #pragma unroll
        for (int t = 0; t < 12; ++t) {
            const int c = lane + t * 32;
            nsr[c] = (x[t] - mu) * rstd * nw[c] + nb[c];
        }
    }
    __syncthreads();

    // ---- projections: thread = (oc, c-quarter); 1 weight LDG -> 2 FMAs ----
    const int oc  = tid & 63;          // 0..31 left, 32..63 right
    const int q   = tid >> 6;
    const int col = oc & 31;
    const float* w = (oc < 32) ? wl : wr;
    float d0 = 0.f, d1 = 0.f;
    const int c0 = q * (C_IN / 4);
    #pragma unroll 8
    for (int c = c0; c < c0 + C_IN / 4; ++c) {
        const float wv = w[c * D + col];
        d0 = fmaf(s_norm[c], wv, d0);
        d1 = fmaf(s_norm[C_IN + c], wv, d1);
    }
    red[tid] = make_float2(d0, d1);
    __syncthreads();
    if (tid < 128) {
        red[tid].x += red[tid + 128].x;
        red[tid].y += red[tid + 128].y;
    }
    __syncthreads();
    if (tid < 64) {
        const float2 a = red[tid];
        const float2 b2 = red[tid + 64];
        const float bias = (oc < 32) ? bl[col] : br[col];
        const float r0 = mask[l0]     * (a.x + b2.x + bias);
        const float r1 = mask[l0 + 1] * (a.y + b2.y + bias);
        if (oc < 32) {
            g_lh[l0 * D + col]       = __float2half_rn(r0);
            g_lh[(l0 + 1) * D + col] = __float2half_rn(r1);
        } else {
            g_right[l0 * D + col]       = r0;
            g_right[(l0 + 1) * D + col] = r1;
        }
    }
}

// ---------------- Kernel C: mma.sync batched GEMM (fp16, K=32) ----------------
// EXACT R13 kernel (measured 57.3us) — do not modify.
#define RSTRIDE 80
#define BTILEB  10240
#define ATILEB  2560           // 32 rows x 80 B
#define STAGEB  16384          // 32 rows x 512 B
#define SOFF_LIN   0
#define SOFF_B     512
#define SOFF_A0    (512 + BTILEB)
#define SOFF_A1    (512 + BTILEB + ATILEB)
#define SOFF_STG   (512 + BTILEB + 2 * ATILEB)       // 15872
#define SMEM_PAIR  (SOFF_STG + 2 * STAGEB)           // 48640

__global__ void __launch_bounds__(256, 4) pair_kernel(
    const float* __restrict__ wo, const float* __restrict__ bo,
    float* __restrict__ out)
{
    extern __shared__ char smem[];
    __shared__ float r_s[D];
    const uint32_t sb = smem_u32(smem);
    const uint32_t sB = sb + SOFF_B;
    float* lin_s = reinterpret_cast<float*>(smem + SOFF_LIN);

    const int tid = threadIdx.x;
    const int wid = tid >> 5;
    const int lane = tid & 31;
    const int mw = wid & 1;          // m position: rows mw*16 within 32-row tile
    const int nq = wid >> 1;         // e quadrant: cols nq*32
    const int i = blockIdx.y;
    const int jh = blockIdx.x;       // 0/1 j-half

    if (tid < D) r_s[tid] = g_right[i * D + tid];
    __syncthreads();

    // ---- build B tile in smem (threads 0..127) + lin ----
    if (tid < E) {
        const int e = tid;
        float acc = 0.0f;
        alignas(16) __half hi[D];
        #pragma unroll
        for (int d = 0; d < D; ++d) {
            const float w1 = wo[d * E + e];
            const float w2 = wo[(D + d) * E + e];
            const float rd = r_s[d];
            hi[d] = __float2half_rn(fmaf(rd, w1, w2));
            acc = fmaf(rd, w2, acc);
        }
        lin_s[e] = bo[e] - acc;
        const uint4* h4 = reinterpret_cast<const uint4*>(hi);
        char* rowp = smem + SOFF_B + e * RSTRIDE;
        #pragma unroll
        for (int c = 0; c < 4; ++c)
            *reinterpret_cast<uint4*>(rowp + c * 16) = h4[c];
    }

    // ---- first A tile (32 rows) via cp.async into buffer 0 ----
    const __half* gA = g_lh;
    const int jbase = jh * 384;
    if (tid < 128) {
        const int row = tid >> 2, c = tid & 3;
        CP_ASYNC16(sb + SOFF_A0 + row * RSTRIDE + c * 16,
                   (const char*)(gA + (jbase + row) * D) + c * 16);
    }
    CP_COMMIT();
    CP_WAIT0();
    __syncthreads();

    // ---- hoist B fragments (32 cols per warp, both k-tiles) ----
    uint32_t bfr[2][4][2];
    #pragma unroll
    for (int kt = 0; kt < 2; ++kt) {
        #pragma unroll
        for (int p = 0; p < 2; ++p) {
            const uint32_t er = nq * 32 + p * 16;
            const uint32_t row = er + (lane & 7) + ((lane >> 4) << 3);
            const uint32_t addr = sB + row * RSTRIDE + kt * 32 + (((lane >> 3) & 1) << 4);
            uint32_t r[4];
            ldsm_x4(r, addr);
            bfr[kt][2 * p][0] = r[0]; bfr[kt][2 * p][1] = r[1];
            bfr[kt][2 * p + 1][0] = r[2]; bfr[kt][2 * p + 1][1] = r[3];
        }
    }

    // per-lane lin float4 (cols lane*4..lane*4+3, for STG phase)
    const float4 lreg = reinterpret_cast<const float4*>(lin_s)[lane];

    for (int jt = 0; jt < 12; ++jt) {
        const int j0 = jbase + jt * 32;
        const uint32_t sA     = sb + ((jt & 1) ? SOFF_A1 : SOFF_A0);
        const uint32_t sAnext = sb + ((jt & 1) ? SOFF_A0 : SOFF_A1);
        const uint32_t sStage = sb + SOFF_STG + ((jt & 1) ? STAGEB : 0);

        // ---- mainloop: 2 k-tiles of 16 ----
        float acc[4][4];
        #pragma unroll
        for (int n = 0; n < 4; ++n)
            #pragma unroll
            for (int q = 0; q < 4; ++q) acc[n][q] = 0.0f;

        #pragma unroll
        for (int kt = 0; kt < 2; ++kt) {
            const uint32_t jr = mw * 16 + (lane & 15);
            const uint32_t addr = sA + jr * RSTRIDE + kt * 32 + ((lane >> 4) << 4);
            uint32_t a[4];
            ldsm_x4(a, addr);
            #pragma unroll
            for (int n = 0; n < 4; ++n)
                mma16816(acc[n], a, bfr[kt][n]);
        }

        // ---- prefetch next A tile immediately (latency hidden under STS) ----
        const bool has_next = (jt < 11);
        if (has_next) {
            if (tid < 128) {
                const int j1 = j0 + 32;
                const int row = tid >> 2, c = tid & 3;
                CP_ASYNC16(sAnext + row * RSTRIDE + c * 16,
                           (const char*)(gA + (j1 + row) * D) + c * 16);
            }
            CP_COMMIT();
        }

        // ---- STS raw acc into this tile's stage buffer (conflict-free) ----
        #pragma unroll
        for (int h = 0; h < 2; ++h) {
            const uint32_t r = mw * 16 + (lane >> 2) + 8 * h;
            const uint32_t rbase = sStage + r * 512 + ((lane & 1) << 3);
            const uint32_t sw2 = (r & 7) << 1;
            #pragma unroll
            for (int n = 0; n < 4; ++n) {
                const uint32_t chunk = nq * 8 + n * 2 + ((lane & 3) >> 1);
                const uint32_t addr = rbase + ((chunk ^ sw2) << 4);
                asm volatile("st.shared.v2.f32 [%0], {%1,%2};"
                             :: "r"(addr), "f"(acc[n][2 * h]), "f"(acc[n][2 * h + 1]) : "memory");
            }
        }

        if (has_next) CP_WAIT0();
        __syncthreads();   // single barrier: stage visible + next A ready

        // ---- drain: each warp owns 4 rows; one STG.128 writes a full 512B row ----
        #pragma unroll
        for (int rr = 0; rr < 4; ++rr) {
            const uint32_t r2 = wid * 4 + rr;
            const uint32_t la = sStage + r2 * 512 + (((uint32_t)lane ^ ((r2 & 7) << 1)) << 4);
            float v0, v1, v2, v3;
            asm volatile("ld.shared.v4.f32 {%0,%1,%2,%3}, [%4];"
                         : "=f"(v0), "=f"(v1), "=f"(v2), "=f"(v3) : "r"(la));
            float4 v;
            v.x = v0 + lreg.x; v.y = v1 + lreg.y; v.z = v2 + lreg.z; v.w = v3 + lreg.w;
            *reinterpret_cast<float4*>(out + ((size_t)i * L + j0 + r2) * E + lane * 4) = v;
        }
    }
}

// ---------------- launch ----------------
extern "C" void kernel_launch(void* const* d_in, const int* in_sizes, int n_in,
                              void* d_out, int out_size)
{
    const float* act  = (const float*)d_in[0];
    const float* mask = (const float*)d_in[1];
    const float* nw   = (const float*)d_in[2];
    const float* nb   = (const float*)d_in[3];
    const float* wl   = (const float*)d_in[4];
    const float* bl   = (const float*)d_in[5];
    const float* wr   = (const float*)d_in[6];
    const float* br   = (const float*)d_in[7];
    const float* wo   = (const float*)d_in[8];
    const float* bo   = (const float*)d_in[9];
    float* out = (float*)d_out;

    cudaFuncSetAttribute(pair_kernel, cudaFuncAttributeMaxDynamicSharedMemorySize, SMEM_PAIR);

    ln_proj_kernel<<<L / 2, 256>>>(act, mask, nw, nb, wl, bl, wr, br);
    pair_kernel<<<dim3(2, L), 256, SMEM_PAIR>>>(wo, bo, out);
}